// round 12
// baseline (speedup 1.0000x reference)
#include <cuda_runtime.h>
#include <cuda_bf16.h>
#include <math.h>
#include <stdint.h>

#define Bn 8
#define Tn 1024
#define Cn 512
#define Hn 64
#define NREL 50
#define QK_SCALE 0.125f   // 64^-0.5
#define NQT 16
#define NCH 4
#define NWORK 40

// split-bf16 x ([B*T][C]) for the qkv GEMM A operand
__device__ __nv_bfloat16 g_xh[Bn * Tn * Cn];
__device__ __nv_bfloat16 g_xl[Bn * Tn * Cn];

// split-bf16 q,k (row-major [B*T][64]) and v transposed ([B][64][T])
__device__ __nv_bfloat16 g_qh[Bn * Tn * Hn];
__device__ __nv_bfloat16 g_ql[Bn * Tn * Hn];
__device__ __nv_bfloat16 g_kh[Bn * Tn * Hn];
__device__ __nv_bfloat16 g_kl[Bn * Tn * Hn];
__device__ __nv_bfloat16 g_vth[Bn * Hn * Tn];
__device__ __nv_bfloat16 g_vtl[Bn * Hn * Tn];

// split-bf16 W^T
__device__ __nv_bfloat16 g_wth[192 * Cn];
__device__ __nv_bfloat16 g_wtl[192 * Cn];

// split-KV partials
__device__ float g_pacc[Bn * NQT * NCH][64 * 64];
__device__ float g_pm[Bn * NQT * NCH][64];
__device__ float g_pl[Bn * NQT * NCH][64];

__constant__ unsigned char c_qt[NWORK] = {
    0,1,2,3, 4,4, 5,5, 6,6, 7,7,
    8,8,8, 9,9,9, 10,10,10, 11,11,11,
    12,12,12,12, 13,13,13,13, 14,14,14,14, 15,15,15,15};
__constant__ unsigned char c_ch[NWORK] = {
    0,0,0,0, 0,1, 0,1, 0,1, 0,1,
    0,1,2, 0,1,2, 0,1,2, 0,1,2,
    0,1,2,3, 0,1,2,3, 0,1,2,3, 0,1,2,3};

// ---------------------------------------------------------------------------
// helpers
// ---------------------------------------------------------------------------
__device__ __forceinline__ uint32_t smem_u32(const void* p) {
    uint32_t a;
    asm("{ .reg .u64 t; cvta.to.shared.u64 t, %1; cvt.u32.u64 %0, t; }"
        : "=r"(a) : "l"(p));
    return a;
}
#define LDM_X4(r0, r1, r2, r3, a) \
    asm volatile("ldmatrix.sync.aligned.m8n8.x4.shared.b16 {%0,%1,%2,%3}, [%4];" \
                 : "=r"(r0), "=r"(r1), "=r"(r2), "=r"(r3) : "r"(a))
#define LDM_X2(r0, r1, a) \
    asm volatile("ldmatrix.sync.aligned.m8n8.x2.shared.b16 {%0,%1}, [%2];" \
                 : "=r"(r0), "=r"(r1) : "r"(a))
#define MMA_BF16(d, a, b) \
    asm volatile("mma.sync.aligned.m16n8k16.row.col.f32.bf16.bf16.f32 " \
                 "{%0,%1,%2,%3}, {%4,%5,%6,%7}, {%8,%9}, {%0,%1,%2,%3};" \
                 : "+f"((d)[0]), "+f"((d)[1]), "+f"((d)[2]), "+f"((d)[3]) \
                 : "r"((a)[0]), "r"((a)[1]), "r"((a)[2]), "r"((a)[3]), \
                   "r"((b)[0]), "r"((b)[1]))

__device__ __forceinline__ void cp16(uint32_t s, const void* g) {
    asm volatile("cp.async.cg.shared.global [%0], [%1], 16;" :: "r"(s), "l"(g));
}
#define CP_COMMIT() asm volatile("cp.async.commit_group;" ::: "memory")
#define CP_WAIT0()  asm volatile("cp.async.wait_group 0;" ::: "memory")

__device__ __forceinline__ void split2(float f0, float f1,
                                       uint32_t& h, uint32_t& l) {
    __nv_bfloat16 h0 = __float2bfloat16(f0), h1 = __float2bfloat16(f1);
    __nv_bfloat16 l0 = __float2bfloat16(f0 - __bfloat162float(h0));
    __nv_bfloat16 l1 = __float2bfloat16(f1 - __bfloat162float(h1));
    __nv_bfloat162 hh(h0, h1), ll(l0, l1);
    h = *(uint32_t*)&hh; l = *(uint32_t*)&ll;
}

// ---------------------------------------------------------------------------
// Split x -> (hi, lo) bf16. grid 4096 x 256, 4 floats/thread, coalesced.
// ---------------------------------------------------------------------------
__global__ __launch_bounds__(256) void cvt_x_kernel(const float* __restrict__ x)
{
    int i = blockIdx.x * 256 + threadIdx.x;
    float4 v = ((const float4*)x)[i];
    uint32_t h0, l0, h1, l1;
    split2(v.x, v.y, h0, l0);
    split2(v.z, v.w, h1, l1);
    ((uint2*)g_xh)[i] = make_uint2(h0, h1);
    ((uint2*)g_xl)[i] = make_uint2(l0, l1);
}

// ---------------------------------------------------------------------------
// Weight convert + transpose. grid 24, 1024 threads.
// ---------------------------------------------------------------------------
__global__ __launch_bounds__(1024) void cvt_w_kernel(
    const float* __restrict__ Wq, const float* __restrict__ Wk,
    const float* __restrict__ Wv)
{
    __shared__ __nv_bfloat16 th[64][72];   // [n][k]
    __shared__ __nv_bfloat16 tl[64][72];
    const int mat = blockIdx.x >> 3, kt = blockIdx.x & 7;
    const float* W = (mat == 0) ? Wq : (mat == 1 ? Wk : Wv);
    const int tid = threadIdx.x;

    {
        int k = tid >> 4, nn = (tid & 15) << 2;
        float4 v = *(const float4*)(W + (size_t)(kt * 64 + k) * Hn + nn);
        float vv[4] = {v.x, v.y, v.z, v.w};
#pragma unroll
        for (int j = 0; j < 4; j++) {
            __nv_bfloat16 h = __float2bfloat16(vv[j]);
            th[nn + j][k] = h;
            tl[nn + j][k] = __float2bfloat16(vv[j] - __bfloat162float(h));
        }
    }
    __syncthreads();
    {
        int n = (tid & 511) >> 3, kk = (tid & 7) << 3;
        size_t dst = (size_t)(mat * 64 + n) * Cn + kt * 64 + kk;
        if (tid < 512) *(uint4*)(g_wth + dst) = *(uint4*)&th[n][kk];
        else           *(uint4*)(g_wtl + dst) = *(uint4*)&tl[n][kk];
    }
}

// ---------------------------------------------------------------------------
// QKV projection on mma.sync bf16 (split hi/lo), cp.async double-buffered.
// grid 128, 256 threads. Per CTA: M=64, N=192 (q|k|v), K in 8 chunks of 64.
// ---------------------------------------------------------------------------
#define PAD 72
#define QB_AH 0
#define QB_AL 9216
#define QB_BH 18432
#define QB_BL 46080
#define QBUF  73728
#define QKV_SMEM 147456

__device__ __forceinline__ void prefetch_qkv(uint32_t sb, uint32_t buf,
                                             int tid, int m0, int kc)
{
#pragma unroll
    for (int it = 0; it < 2; it++) {
        int f = it * 256 + tid;
        int r = f >> 3, cq = f & 7;
        uint32_t off = (uint32_t)(r * PAD + cq * 8) * 2;
        cp16(sb + buf + QB_AH + off, g_xh + (size_t)(m0 + r) * Cn + kc + cq * 8);
        cp16(sb + buf + QB_AL + off, g_xl + (size_t)(m0 + r) * Cn + kc + cq * 8);
    }
#pragma unroll
    for (int it = 0; it < 6; it++) {
        int f = it * 256 + tid;
        int n = f >> 3, cq = f & 7;
        uint32_t off = (uint32_t)(n * PAD + cq * 8) * 2;
        cp16(sb + buf + QB_BH + off, g_wth + (size_t)n * Cn + kc + cq * 8);
        cp16(sb + buf + QB_BL + off, g_wtl + (size_t)n * Cn + kc + cq * 8);
    }
}

__global__ __launch_bounds__(256, 1) void qkv_mma_kernel()
{
    extern __shared__ char smem[];
    const uint32_t sb = smem_u32(smem);
    const int tid = threadIdx.x;
    const int wid = tid >> 5, lane = tid & 31;
    const int wm = wid >> 2, wn = wid & 3;
    const int m0 = blockIdx.x * 64;

    float acc[2][6][4];
#pragma unroll
    for (int mt = 0; mt < 2; mt++)
#pragma unroll
        for (int nt = 0; nt < 6; nt++)
#pragma unroll
            for (int e = 0; e < 4; e++) acc[mt][nt][e] = 0.f;

    const int aq = lane >> 3, ai = lane & 7;
    const int arow_off = (aq & 1) * 8 + ai;
    const int akoff = (aq >> 1) * 8;
    const int bi = lane & 7, bh8 = ((lane >> 3) & 1) * 8;

    prefetch_qkv(sb, 0, tid, m0, 0);
    CP_COMMIT();

    for (int c = 0; c < 8; c++) {
        const uint32_t cur = (c & 1) ? QBUF : 0;
        CP_WAIT0();
        __syncthreads();
        if (c < 7) {
            prefetch_qkv(sb, (c & 1) ? 0 : QBUF, tid, m0, (c + 1) * 64);
            CP_COMMIT();
        }

#pragma unroll
        for (int ks = 0; ks < 4; ks++) {
            const int K = ks * 16;
            uint32_t ah[2][4], al[2][4];
#pragma unroll
            for (int mt = 0; mt < 2; mt++) {
                uint32_t ao = (uint32_t)((wm * 32 + mt * 16 + arow_off) * PAD
                                         + K + akoff) * 2;
                LDM_X4(ah[mt][0], ah[mt][1], ah[mt][2], ah[mt][3],
                       sb + cur + QB_AH + ao);
                LDM_X4(al[mt][0], al[mt][1], al[mt][2], al[mt][3],
                       sb + cur + QB_AL + ao);
            }
#pragma unroll
            for (int nt = 0; nt < 6; nt++) {
                uint32_t bo = (uint32_t)((wn * 48 + nt * 8 + bi) * PAD
                                         + K + bh8) * 2;
                uint32_t bh[2], bl[2];
                LDM_X2(bh[0], bh[1], sb + cur + QB_BH + bo);
                LDM_X2(bl[0], bl[1], sb + cur + QB_BL + bo);
#pragma unroll
                for (int mt = 0; mt < 2; mt++) {
                    MMA_BF16(acc[mt][nt], ah[mt], bh);
                    MMA_BF16(acc[mt][nt], ah[mt], bl);
                    MMA_BF16(acc[mt][nt], al[mt], bh);
                }
            }
        }
    }

    const int g = lane >> 2, t = lane & 3;
#pragma unroll
    for (int mt = 0; mt < 2; mt++) {
#pragma unroll
        for (int nt = 0; nt < 6; nt++) {
            const int c0 = wn * 48 + nt * 8 + 2 * t;
            const size_t row = (size_t)m0 + wm * 32 + mt * 16 + g;
            if (c0 < 128) {
                __nv_bfloat16* dh = (c0 < 64) ? g_qh : g_kh;
                __nv_bfloat16* dl = (c0 < 64) ? g_ql : g_kl;
                const int cc = c0 & 63;
                uint32_t h, l;
                split2(acc[mt][nt][0], acc[mt][nt][1], h, l);
                *(uint32_t*)(dh + row * Hn + cc) = h;
                *(uint32_t*)(dl + row * Hn + cc) = l;
                split2(acc[mt][nt][2], acc[mt][nt][3], h, l);
                *(uint32_t*)(dh + (row + 8) * Hn + cc) = h;
                *(uint32_t*)(dl + (row + 8) * Hn + cc) = l;
            } else {
                const int cc = c0 - 128;
                const size_t bb = row >> 10;
#pragma unroll
                for (int rr = 0; rr < 2; rr++) {
                    const size_t s = (row + rr * 8) & 1023;
                    float f0 = acc[mt][nt][rr * 2], f1 = acc[mt][nt][rr * 2 + 1];
                    __nv_bfloat16 h0 = __float2bfloat16(f0);
                    __nv_bfloat16 h1 = __float2bfloat16(f1);
                    g_vth[bb * 65536 + (size_t)cc * 1024 + s] = h0;
                    g_vtl[bb * 65536 + (size_t)cc * 1024 + s] =
                        __float2bfloat16(f0 - __bfloat162float(h0));
                    g_vth[bb * 65536 + (size_t)(cc + 1) * 1024 + s] = h1;
                    g_vtl[bb * 65536 + (size_t)(cc + 1) * 1024 + s] =
                        __float2bfloat16(f1 - __bfloat162float(h1));
                }
            }
        }
    }
}

// ---------------------------------------------------------------------------
// Fragment-resident flash attention with cp.async double-buffered K/V.
// grid (40, 8), 128 threads. (unchanged from R11)
// ---------------------------------------------------------------------------
#define PADH 72
#define SM_QH  0
#define SM_QL  9216
#define SM_B0  18432       // per-buf: KH +0, KL +9216, VTH +18432, VTL +27648
#define SM_B1  55296
#define SM_DS  92160       // fp32 [64][68]
#define ATTN_SMEM 109568

__device__ __forceinline__ void prefetch_kv(uint32_t sb, uint32_t buf,
                                            int tid, int b, int kt)
{
    const int krow0 = b * Tn + kt * 64;
#pragma unroll
    for (int it = 0; it < 4; it++) {
        int f = it * 128 + tid;
        int r = f >> 3, cq = f & 7;
        uint32_t off = (uint32_t)(r * PADH + cq * 8) * 2;
        cp16(sb + buf + off,
             g_kh + (size_t)(krow0 + r) * Hn + cq * 8);
        cp16(sb + buf + 9216 + off,
             g_kl + (size_t)(krow0 + r) * Hn + cq * 8);
        cp16(sb + buf + 18432 + off,
             g_vth + (size_t)b * 65536 + (size_t)r * 1024 + kt * 64 + cq * 8);
        cp16(sb + buf + 27648 + off,
             g_vtl + (size_t)b * 65536 + (size_t)r * 1024 + kt * 64 + cq * 8);
    }
}

__global__ __launch_bounds__(128) void attn_part_kernel(
    const float* __restrict__ rpe, float* __restrict__ out)
{
    extern __shared__ char smem[];
    const uint32_t sb = smem_u32(smem);
    float* Ds = (float*)(smem + SM_DS);

    const int w = blockIdx.x, b = blockIdx.y;
    const int qt = c_qt[w], ch = c_ch[w];
    const int kt0 = ch * 4;
    const int kt1 = min(qt, kt0 + 3);
    const int nch = (qt >> 2) + 1;

    const int tid = threadIdx.x;
    const int wid = tid >> 5, lane = tid & 31;
    const int g = lane >> 2, t = lane & 3;
    const int aq = lane >> 3, ai = lane & 7;
    const int arow_off = (aq & 1) * 8 + ai;
    const int akoff = (aq >> 1) * 8;
    const int bq_row = ((lane >> 4) & 1) * 8 + (lane & 7);
    const int bq_col = ((lane >> 3) & 1) * 8;
    const int wq = wid * 16;
    const int row0 = b * Tn + qt * 64;

    prefetch_kv(sb, SM_B1, tid, b, kt0);
    CP_COMMIT();

#pragma unroll
    for (int it = 0; it < 4; it++) {
        int f = it * 128 + tid;
        int r = f >> 3, cq = f & 7;
        uint32_t off = (uint32_t)(r * PADH + cq * 8) * 2;
        *(uint4*)(smem + SM_QH + off) =
            *(const uint4*)(g_qh + (size_t)(row0 + r) * Hn + cq * 8);
        *(uint4*)(smem + SM_QL + off) =
            *(const uint4*)(g_ql + (size_t)(row0 + r) * Hn + cq * 8);
    }
#pragma unroll
    for (int it = 0; it < 8; it++) {
        int f = it * 128 + tid;
        int r = f >> 4, cq = (f & 15) << 2;
        float4 v = make_float4(0.f, 0.f, 0.f, 0.f);
        if (r < NREL) v = *(const float4*)(rpe + (size_t)r * Hn + cq);
        uint32_t h0, l0, h1, l1;
        split2(v.x, v.y, h0, l0);
        split2(v.z, v.w, h1, l1);
        uint32_t off = (uint32_t)(r * PADH + cq) * 2;
        *(uint2*)(smem + SM_B0 + off) = make_uint2(h0, h1);
        *(uint2*)(smem + SM_B0 + 9216 + off) = make_uint2(l0, l1);
    }
    __syncthreads();

    // ---- bias GEMM: Ds = Q E^T ----
    {
        float dacc[8][4];
#pragma unroll
        for (int nt = 0; nt < 8; nt++)
#pragma unroll
            for (int e = 0; e < 4; e++) dacc[nt][e] = 0.f;
#pragma unroll
        for (int ks = 0; ks < 4; ks++) {
            const int K = ks * 16;
            uint32_t ah[4], al[4];
            uint32_t ao = (uint32_t)((wq + arow_off) * PADH + K + akoff) * 2;
            LDM_X4(ah[0], ah[1], ah[2], ah[3], sb + SM_QH + ao);
            LDM_X4(al[0], al[1], al[2], al[3], sb + SM_QL + ao);
#pragma unroll
            for (int np = 0; np < 4; np++) {
                uint32_t bo = (uint32_t)((np * 16 + bq_row) * PADH + K + bq_col) * 2;
                uint32_t eh[4], el[4];
                LDM_X4(eh[0], eh[1], eh[2], eh[3], sb + SM_B0 + bo);
                LDM_X4(el[0], el[1], el[2], el[3], sb + SM_B0 + 9216 + bo);
                MMA_BF16(dacc[2 * np], ah, eh);
                MMA_BF16(dacc[2 * np], ah, el);
                MMA_BF16(dacc[2 * np], al, eh);
                MMA_BF16(dacc[2 * np + 1], ah, eh + 2);
                MMA_BF16(dacc[2 * np + 1], ah, el + 2);
                MMA_BF16(dacc[2 * np + 1], al, eh + 2);
            }
        }
#pragma unroll
        for (int nt = 0; nt < 8; nt++) {
            int col = nt * 8 + 2 * t;
            *(float2*)&Ds[(wq + g) * 68 + col] =
                make_float2(dacc[nt][0], dacc[nt][1]);
            *(float2*)&Ds[(wq + g + 8) * 68 + col] =
                make_float2(dacc[nt][2], dacc[nt][3]);
        }
    }

    float m0 = -INFINITY, m1 = -INFINITY, l0 = 0.f, l1 = 0.f;
    float oacc[8][4];
#pragma unroll
    for (int nt = 0; nt < 8; nt++)
#pragma unroll
        for (int e = 0; e < 4; e++) oacc[nt][e] = 0.f;

    const int lr0 = wq + g, lr1 = wq + g + 8;
    const int tg0 = qt * 64 + lr0, tg1 = qt * 64 + lr1;

    for (int i = 0; i <= kt1 - kt0; i++) {
        const int kt = kt0 + i;
        const uint32_t cur = (i & 1) ? SM_B0 : SM_B1;

        CP_WAIT0();
        __syncthreads();
        if (kt < kt1) {
            prefetch_kv(sb, (i & 1) ? SM_B1 : SM_B0, tid, b, kt + 1);
            CP_COMMIT();
        }

        float sacc[8][4];
#pragma unroll
        for (int nt = 0; nt < 8; nt++)
#pragma unroll
            for (int e = 0; e < 4; e++) sacc[nt][e] = 0.f;
#pragma unroll
        for (int ks = 0; ks < 4; ks++) {
            const int K = ks * 16;
            uint32_t ah[4], al[4];
            uint32_t ao = (uint32_t)((wq + arow_off) * PADH + K + akoff) * 2;
            LDM_X4(ah[0], ah[1], ah[2], ah[3], sb + SM_QH + ao);
            LDM_X4(al[0], al[1], al[2], al[3], sb + SM_QL + ao);
#pragma unroll
            for (int np = 0; np < 4; np++) {
                uint32_t bo = (uint32_t)((np * 16 + bq_row) * PADH + K + bq_col) * 2;
                uint32_t kh[4], kl[4];
                LDM_X4(kh[0], kh[1], kh[2], kh[3], sb + cur + bo);
                LDM_X4(kl[0], kl[1], kl[2], kl[3], sb + cur + 9216 + bo);
                MMA_BF16(sacc[2 * np], ah, kh);
                MMA_BF16(sacc[2 * np], ah, kl);
                MMA_BF16(sacc[2 * np], al, kh);
                MMA_BF16(sacc[2 * np + 1], ah, kh + 2);
                MMA_BF16(sacc[2 * np + 1], ah, kl + 2);
                MMA_BF16(sacc[2 * np + 1], al, kh + 2);
            }
        }

#pragma unroll
        for (int nt = 0; nt < 8; nt++) {
            const int s0g = kt * 64 + nt * 8 + 2 * t;
#pragma unroll
            for (int e = 0; e < 4; e++) {
                const int sg = s0g + (e & 1);
                const int tg = (e < 2) ? tg0 : tg1;
                const int lr = (e < 2) ? lr0 : lr1;
                int rel = 49 + sg - tg;
                rel = rel < 0 ? 0 : (rel > 49 ? 49 : rel);
                float bias = Ds[lr * 68 + rel];
                sacc[nt][e] = (sg > tg) ? -INFINITY
                                        : fmaf(sacc[nt][e], QK_SCALE, bias);
            }
        }

        float mx0 = -INFINITY, mx1 = -INFINITY;
#pragma unroll
        for (int nt = 0; nt < 8; nt++) {
            mx0 = fmaxf(mx0, fmaxf(sacc[nt][0], sacc[nt][1]));
            mx1 = fmaxf(mx1, fmaxf(sacc[nt][2], sacc[nt][3]));
        }
        mx0 = fmaxf(mx0, __shfl_xor_sync(0xffffffffu, mx0, 1));
        mx0 = fmaxf(mx0, __shfl_xor_sync(0xffffffffu, mx0, 2));
        mx1 = fmaxf(mx1, __shfl_xor_sync(0xffffffffu, mx1, 1));
        mx1 = fmaxf(mx1, __shfl_xor_sync(0xffffffffu, mx1, 2));
        float mn0 = fmaxf(m0, mx0), mn1 = fmaxf(m1, mx1);
        float corr0 = __expf(m0 - mn0), corr1 = __expf(m1 - mn1);
        float s0 = 0.f, s1 = 0.f;
#pragma unroll
        for (int nt = 0; nt < 8; nt++) {
            sacc[nt][0] = __expf(sacc[nt][0] - mn0);
            sacc[nt][1] = __expf(sacc[nt][1] - mn0);
            sacc[nt][2] = __expf(sacc[nt][2] - mn1);
            sacc[nt][3] = __expf(sacc[nt][3] - mn1);
            s0 += sacc[nt][0] + sacc[nt][1];
            s1 += sacc[nt][2] + sacc[nt][3];
        }
        s0 += __shfl_xor_sync(0xffffffffu, s0, 1);
        s0 += __shfl_xor_sync(0xffffffffu, s0, 2);
        s1 += __shfl_xor_sync(0xffffffffu, s1, 1);
        s1 += __shfl_xor_sync(0xffffffffu, s1, 2);
        l0 = l0 * corr0 + s0; m0 = mn0;
        l1 = l1 * corr1 + s1; m1 = mn1;
#pragma unroll
        for (int nt = 0; nt < 8; nt++) {
            oacc[nt][0] *= corr0; oacc[nt][1] *= corr0;
            oacc[nt][2] *= corr1; oacc[nt][3] *= corr1;
        }

#pragma unroll
        for (int ks = 0; ks < 4; ks++) {
            uint32_t ph[4], pl[4];
            split2(sacc[2 * ks][0],     sacc[2 * ks][1],     ph[0], pl[0]);
            split2(sacc[2 * ks][2],     sacc[2 * ks][3],     ph[1], pl[1]);
            split2(sacc[2 * ks + 1][0], sacc[2 * ks + 1][1], ph[2], pl[2]);
            split2(sacc[2 * ks + 1][2], sacc[2 * ks + 1][3], ph[3], pl[3]);
            const int K = ks * 16;
#pragma unroll
            for (int np = 0; np < 4; np++) {
                uint32_t bo = (uint32_t)((np * 16 + bq_row) * PADH + K + bq_col) * 2;
                uint32_t vh[4], vl[4];
                LDM_X4(vh[0], vh[1], vh[2], vh[3], sb + cur + 18432 + bo);
                LDM_X4(vl[0], vl[1], vl[2], vl[3], sb + cur + 27648 + bo);
                MMA_BF16(oacc[2 * np], ph, vh);
                MMA_BF16(oacc[2 * np], ph, vl);
                MMA_BF16(oacc[2 * np], pl, vh);
                MMA_BF16(oacc[2 * np + 1], ph, vh + 2);
                MMA_BF16(oacc[2 * np + 1], ph, vl + 2);
                MMA_BF16(oacc[2 * np + 1], pl, vh + 2);
            }
        }
    }

    if (nch == 1) {
        float i0 = 1.f / l0, i1 = 1.f / l1;
#pragma unroll
        for (int nt = 0; nt < 8; nt++) {
            int col = nt * 8 + 2 * t;
            *(float2*)(out + (size_t)(row0 + lr0) * Hn + col) =
                make_float2(oacc[nt][0] * i0, oacc[nt][1] * i0);
            *(float2*)(out + (size_t)(row0 + lr1) * Hn + col) =
                make_float2(oacc[nt][2] * i1, oacc[nt][3] * i1);
        }
        return;
    }

    const int slot = (b * NQT + qt) * NCH + ch;
    float* pa = g_pacc[slot];
#pragma unroll
    for (int nt = 0; nt < 8; nt++) {
        int col = nt * 8 + 2 * t;
        *(float2*)(pa + lr0 * 64 + col) = make_float2(oacc[nt][0], oacc[nt][1]);
        *(float2*)(pa + lr1 * 64 + col) = make_float2(oacc[nt][2], oacc[nt][3]);
    }
    if (t == 0) {
        g_pm[slot][lr0] = m0; g_pm[slot][lr1] = m1;
        g_pl[slot][lr0] = l0; g_pl[slot][lr1] = l1;
    }
}

// ---------------------------------------------------------------------------
// Combine partials. grid (12, 8) for qt=4..15, 1024 threads.
// ---------------------------------------------------------------------------
__global__ __launch_bounds__(1024) void combine_kernel(float* __restrict__ out)
{
    const int qt = blockIdx.x + 4, b = blockIdx.y;
    const int nch = (qt >> 2) + 1;
    const int base = (b * NQT + qt) * NCH;
    const int tid = threadIdx.x;
    const int r = tid >> 4;
    const int hc = (tid & 15) << 2;

    float m[NCH], l[NCH];
    float4 v[NCH];
#pragma unroll
    for (int c = 0; c < NCH; c++) {
        bool p = c < nch;
        m[c] = p ? g_pm[base + c][r] : -INFINITY;
        l[c] = p ? g_pl[base + c][r] : 0.f;
        v[c] = p ? *(const float4*)(g_pacc[base + c] + r * 64 + hc)
                 : make_float4(0.f, 0.f, 0.f, 0.f);
    }
    float M = fmaxf(fmaxf(m[0], m[1]), fmaxf(m[2], m[3]));
    float wgt[NCH], L = 0.f;
#pragma unroll
    for (int c = 0; c < NCH; c++) {
        wgt[c] = __expf(m[c] - M);
        L = fmaf(l[c], wgt[c], L);
    }
    float invL = 1.f / L;
    float4 o = make_float4(0.f, 0.f, 0.f, 0.f);
#pragma unroll
    for (int c = 0; c < NCH; c++) {
        float wc = wgt[c] * invL;
        o.x = fmaf(wc, v[c].x, o.x);
        o.y = fmaf(wc, v[c].y, o.y);
        o.z = fmaf(wc, v[c].z, o.z);
        o.w = fmaf(wc, v[c].w, o.w);
    }
    *(float4*)(out + (size_t)(b * Tn + qt * 64 + r) * Hn + hc) = o;
}

extern "C" void kernel_launch(void* const* d_in, const int* in_sizes, int n_in,
                              void* d_out, int out_size)
{
    const float* x   = (const float*)d_in[0];
    const float* Wq  = (const float*)d_in[1];
    const float* Wk  = (const float*)d_in[2];
    const float* Wv  = (const float*)d_in[3];
    const float* rpe = (const float*)d_in[4];
    float* out = (float*)d_out;

    cudaFuncSetAttribute(qkv_mma_kernel,
                         cudaFuncAttributeMaxDynamicSharedMemorySize, QKV_SMEM);
    cudaFuncSetAttribute(attn_part_kernel,
                         cudaFuncAttributeMaxDynamicSharedMemorySize, ATTN_SMEM);

    cvt_x_kernel<<<4096, 256>>>(x);
    cvt_w_kernel<<<24, 1024>>>(Wq, Wk, Wv);
    qkv_mma_kernel<<<128, 256, QKV_SMEM>>>();
    attn_part_kernel<<<dim3(NWORK, 8), 128, ATTN_SMEM>>>(rpe, out);
    combine_kernel<<<dim3(12, 8), 1024>>>(out);
}

// round 13
// speedup vs baseline: 1.0576x; 1.0576x over previous
#include <cuda_runtime.h>
#include <cuda_bf16.h>
#include <math.h>
#include <stdint.h>

#define Bn 8
#define Tn 1024
#define Cn 512
#define Hn 64
#define NREL 50
#define QK_SCALE 0.125f   // 64^-0.5
#define NQT 16
#define NCH 8             // max kv-chunks per q-tile (128 keys per chunk)
#define NWORK 72          // sum over qt of ceil((qt+1)/2)

// split-bf16 q,k (row-major [B*T][64]) and v transposed ([B][64][T])
__device__ __nv_bfloat16 g_qh[Bn * Tn * Hn];
__device__ __nv_bfloat16 g_ql[Bn * Tn * Hn];
__device__ __nv_bfloat16 g_kh[Bn * Tn * Hn];
__device__ __nv_bfloat16 g_kl[Bn * Tn * Hn];
__device__ __nv_bfloat16 g_vth[Bn * Hn * Tn];
__device__ __nv_bfloat16 g_vtl[Bn * Hn * Tn];

// split-bf16 W^T
__device__ __nv_bfloat16 g_wth[192 * Cn];
__device__ __nv_bfloat16 g_wtl[192 * Cn];

// split-KV partials
__device__ float g_pacc[Bn * NQT * NCH][64 * 64];
__device__ float g_pm[Bn * NQT * NCH][64];
__device__ float g_pl[Bn * NQT * NCH][64];

__constant__ unsigned char c_qt[NWORK] = {
    0, 1, 2,2, 3,3, 4,4,4, 5,5,5,
    6,6,6,6, 7,7,7,7, 8,8,8,8,8, 9,9,9,9,9,
    10,10,10,10,10,10, 11,11,11,11,11,11,
    12,12,12,12,12,12,12, 13,13,13,13,13,13,13,
    14,14,14,14,14,14,14,14, 15,15,15,15,15,15,15,15};
__constant__ unsigned char c_ch[NWORK] = {
    0, 0, 0,1, 0,1, 0,1,2, 0,1,2,
    0,1,2,3, 0,1,2,3, 0,1,2,3,4, 0,1,2,3,4,
    0,1,2,3,4,5, 0,1,2,3,4,5,
    0,1,2,3,4,5,6, 0,1,2,3,4,5,6,
    0,1,2,3,4,5,6,7, 0,1,2,3,4,5,6,7};

// ---------------------------------------------------------------------------
// helpers
// ---------------------------------------------------------------------------
__device__ __forceinline__ uint32_t smem_u32(const void* p) {
    uint32_t a;
    asm("{ .reg .u64 t; cvta.to.shared.u64 t, %1; cvt.u32.u64 %0, t; }"
        : "=r"(a) : "l"(p));
    return a;
}
#define LDM_X4(r0, r1, r2, r3, a) \
    asm volatile("ldmatrix.sync.aligned.m8n8.x4.shared.b16 {%0,%1,%2,%3}, [%4];" \
                 : "=r"(r0), "=r"(r1), "=r"(r2), "=r"(r3) : "r"(a))
#define LDM_X2(r0, r1, a) \
    asm volatile("ldmatrix.sync.aligned.m8n8.x2.shared.b16 {%0,%1}, [%2];" \
                 : "=r"(r0), "=r"(r1) : "r"(a))
#define MMA_BF16(d, a, b) \
    asm volatile("mma.sync.aligned.m16n8k16.row.col.f32.bf16.bf16.f32 " \
                 "{%0,%1,%2,%3}, {%4,%5,%6,%7}, {%8,%9}, {%0,%1,%2,%3};" \
                 : "+f"((d)[0]), "+f"((d)[1]), "+f"((d)[2]), "+f"((d)[3]) \
                 : "r"((a)[0]), "r"((a)[1]), "r"((a)[2]), "r"((a)[3]), \
                   "r"((b)[0]), "r"((b)[1]))

__device__ __forceinline__ void cp16(uint32_t s, const void* g) {
    asm volatile("cp.async.cg.shared.global [%0], [%1], 16;" :: "r"(s), "l"(g));
}
#define CP_COMMIT() asm volatile("cp.async.commit_group;" ::: "memory")
#define CP_WAIT0()  asm volatile("cp.async.wait_group 0;" ::: "memory")

__device__ __forceinline__ void split2(float f0, float f1,
                                       uint32_t& h, uint32_t& l) {
    __nv_bfloat16 h0 = __float2bfloat16(f0), h1 = __float2bfloat16(f1);
    __nv_bfloat16 l0 = __float2bfloat16(f0 - __bfloat162float(h0));
    __nv_bfloat16 l1 = __float2bfloat16(f1 - __bfloat162float(h1));
    __nv_bfloat162 hh(h0, h1), ll(l0, l1);
    h = *(uint32_t*)&hh; l = *(uint32_t*)&ll;
}

// ---------------------------------------------------------------------------
// Weight convert + transpose. grid 24, 1024 threads.
// ---------------------------------------------------------------------------
__global__ __launch_bounds__(1024) void cvt_w_kernel(
    const float* __restrict__ Wq, const float* __restrict__ Wk,
    const float* __restrict__ Wv)
{
    __shared__ __nv_bfloat16 th[64][72];   // [n][k]
    __shared__ __nv_bfloat16 tl[64][72];
    const int mat = blockIdx.x >> 3, kt = blockIdx.x & 7;
    const float* W = (mat == 0) ? Wq : (mat == 1 ? Wk : Wv);
    const int tid = threadIdx.x;

    {
        int k = tid >> 4, nn = (tid & 15) << 2;
        float4 v = *(const float4*)(W + (size_t)(kt * 64 + k) * Hn + nn);
        float vv[4] = {v.x, v.y, v.z, v.w};
#pragma unroll
        for (int j = 0; j < 4; j++) {
            __nv_bfloat16 h = __float2bfloat16(vv[j]);
            th[nn + j][k] = h;
            tl[nn + j][k] = __float2bfloat16(vv[j] - __bfloat162float(h));
        }
    }
    __syncthreads();
    {
        int n = (tid & 511) >> 3, kk = (tid & 7) << 3;
        size_t dst = (size_t)(mat * 64 + n) * Cn + kt * 64 + kk;
        if (tid < 512) *(uint4*)(g_wth + dst) = *(uint4*)&th[n][kk];
        else           *(uint4*)(g_wtl + dst) = *(uint4*)&tl[n][kk];
    }
}

// ---------------------------------------------------------------------------
// QKV projection on mma.sync bf16 (split hi/lo). grid 128, 256 threads.
// (R11 version: in-kernel split, synchronous loads)
// ---------------------------------------------------------------------------
#define PAD 72
#define SM_AH 0
#define SM_AL 9216
#define SM_BH 18432
#define SM_BL 46080
#define QKV_SMEM 73728

__global__ __launch_bounds__(256, 1) void qkv_mma_kernel(const float* __restrict__ x)
{
    extern __shared__ char smem[];
    const uint32_t sb = smem_u32(smem);
    const int tid = threadIdx.x;
    const int wid = tid >> 5, lane = tid & 31;
    const int wm = wid >> 2, wn = wid & 3;
    const int m0 = blockIdx.x * 64;

    float acc[2][6][4];
#pragma unroll
    for (int mt = 0; mt < 2; mt++)
#pragma unroll
        for (int nt = 0; nt < 6; nt++)
#pragma unroll
            for (int e = 0; e < 4; e++) acc[mt][nt][e] = 0.f;

    const int aq = lane >> 3, ai = lane & 7;
    const int arow_off = (aq & 1) * 8 + ai;
    const int akoff = (aq >> 1) * 8;
    const int bi = lane & 7, bh8 = ((lane >> 3) & 1) * 8;

    for (int c = 0; c < 8; c++) {
        if (c) __syncthreads();
        const int kc = c * 64;
#pragma unroll
        for (int it = 0; it < 4; it++) {
            int f = it * 256 + tid;
            int r = f >> 4, kq = (f & 15) << 2;
            float4 v = *(const float4*)(x + (size_t)(m0 + r) * Cn + kc + kq);
            uint32_t h0, l0, h1, l1;
            split2(v.x, v.y, h0, l0);
            split2(v.z, v.w, h1, l1);
            uint32_t off = (uint32_t)(r * PAD + kq) * 2;
            *(uint2*)(smem + SM_AH + off) = make_uint2(h0, h1);
            *(uint2*)(smem + SM_AL + off) = make_uint2(l0, l1);
        }
#pragma unroll
        for (int it = 0; it < 6; it++) {
            int f = it * 256 + tid;
            int n = f >> 3, kq = (f & 7) << 3;
            uint32_t off = (uint32_t)(n * PAD + kq) * 2;
            *(uint4*)(smem + SM_BH + off) =
                *(const uint4*)(g_wth + (size_t)n * Cn + kc + kq);
            *(uint4*)(smem + SM_BL + off) =
                *(const uint4*)(g_wtl + (size_t)n * Cn + kc + kq);
        }
        __syncthreads();

#pragma unroll
        for (int ks = 0; ks < 4; ks++) {
            const int K = ks * 16;
            uint32_t ah[2][4], al[2][4];
#pragma unroll
            for (int mt = 0; mt < 2; mt++) {
                uint32_t ao = (uint32_t)((wm * 32 + mt * 16 + arow_off) * PAD
                                         + K + akoff) * 2;
                LDM_X4(ah[mt][0], ah[mt][1], ah[mt][2], ah[mt][3], sb + SM_AH + ao);
                LDM_X4(al[mt][0], al[mt][1], al[mt][2], al[mt][3], sb + SM_AL + ao);
            }
#pragma unroll
            for (int nt = 0; nt < 6; nt++) {
                uint32_t bo = (uint32_t)((wn * 48 + nt * 8 + bi) * PAD
                                         + K + bh8) * 2;
                uint32_t bh[2], bl[2];
                LDM_X2(bh[0], bh[1], sb + SM_BH + bo);
                LDM_X2(bl[0], bl[1], sb + SM_BL + bo);
#pragma unroll
                for (int mt = 0; mt < 2; mt++) {
                    MMA_BF16(acc[mt][nt], ah[mt], bh);
                    MMA_BF16(acc[mt][nt], ah[mt], bl);
                    MMA_BF16(acc[mt][nt], al[mt], bh);
                }
            }
        }
    }

    const int g = lane >> 2, t = lane & 3;
#pragma unroll
    for (int mt = 0; mt < 2; mt++) {
#pragma unroll
        for (int nt = 0; nt < 6; nt++) {
            const int c0 = wn * 48 + nt * 8 + 2 * t;
            const size_t row = (size_t)m0 + wm * 32 + mt * 16 + g;
            if (c0 < 128) {
                __nv_bfloat16* dh = (c0 < 64) ? g_qh : g_kh;
                __nv_bfloat16* dl = (c0 < 64) ? g_ql : g_kl;
                const int cc = c0 & 63;
                uint32_t h, l;
                split2(acc[mt][nt][0], acc[mt][nt][1], h, l);
                *(uint32_t*)(dh + row * Hn + cc) = h;
                *(uint32_t*)(dl + row * Hn + cc) = l;
                split2(acc[mt][nt][2], acc[mt][nt][3], h, l);
                *(uint32_t*)(dh + (row + 8) * Hn + cc) = h;
                *(uint32_t*)(dl + (row + 8) * Hn + cc) = l;
            } else {
                const int cc = c0 - 128;
                const size_t bb = row >> 10;
#pragma unroll
                for (int rr = 0; rr < 2; rr++) {
                    const size_t s = (row + rr * 8) & 1023;
                    float f0 = acc[mt][nt][rr * 2], f1 = acc[mt][nt][rr * 2 + 1];
                    __nv_bfloat16 h0 = __float2bfloat16(f0);
                    __nv_bfloat16 h1 = __float2bfloat16(f1);
                    g_vth[bb * 65536 + (size_t)cc * 1024 + s] = h0;
                    g_vtl[bb * 65536 + (size_t)cc * 1024 + s] =
                        __float2bfloat16(f0 - __bfloat162float(h0));
                    g_vth[bb * 65536 + (size_t)(cc + 1) * 1024 + s] = h1;
                    g_vtl[bb * 65536 + (size_t)(cc + 1) * 1024 + s] =
                        __float2bfloat16(f1 - __bfloat162float(h1));
                }
            }
        }
    }
}

// ---------------------------------------------------------------------------
// Fragment-resident flash attention, cp.async double-buffered K/V.
// grid (72, 8), 128 threads. Chunk = up to 2 key-tiles (576 blocks ~ 3.9/SM).
// ---------------------------------------------------------------------------
#define PADH 72
#define SM_QH  0
#define SM_QL  9216
#define SM_B0  18432       // per-buf: KH +0, KL +9216, VTH +18432, VTL +27648
#define SM_B1  55296
#define SM_DS  92160       // fp32 [64][68]
#define ATTN_SMEM 109568

__device__ __forceinline__ void prefetch_kv(uint32_t sb, uint32_t buf,
                                            int tid, int b, int kt)
{
    const int krow0 = b * Tn + kt * 64;
#pragma unroll
    for (int it = 0; it < 4; it++) {
        int f = it * 128 + tid;
        int r = f >> 3, cq = f & 7;
        uint32_t off = (uint32_t)(r * PADH + cq * 8) * 2;
        cp16(sb + buf + off,
             g_kh + (size_t)(krow0 + r) * Hn + cq * 8);
        cp16(sb + buf + 9216 + off,
             g_kl + (size_t)(krow0 + r) * Hn + cq * 8);
        cp16(sb + buf + 18432 + off,
             g_vth + (size_t)b * 65536 + (size_t)r * 1024 + kt * 64 + cq * 8);
        cp16(sb + buf + 27648 + off,
             g_vtl + (size_t)b * 65536 + (size_t)r * 1024 + kt * 64 + cq * 8);
    }
}

__global__ __launch_bounds__(128) void attn_part_kernel(
    const float* __restrict__ rpe, float* __restrict__ out)
{
    extern __shared__ char smem[];
    const uint32_t sb = smem_u32(smem);
    float* Ds = (float*)(smem + SM_DS);

    const int w = blockIdx.x, b = blockIdx.y;
    const int qt = c_qt[w], ch = c_ch[w];
    const int kt0 = ch * 2;
    const int kt1 = min(qt, kt0 + 1);
    const int nch = (qt >> 1) + 1;

    const int tid = threadIdx.x;
    const int wid = tid >> 5, lane = tid & 31;
    const int g = lane >> 2, t = lane & 3;
    const int aq = lane >> 3, ai = lane & 7;
    const int arow_off = (aq & 1) * 8 + ai;
    const int akoff = (aq >> 1) * 8;
    const int bq_row = ((lane >> 4) & 1) * 8 + (lane & 7);
    const int bq_col = ((lane >> 3) & 1) * 8;
    const int wq = wid * 16;
    const int row0 = b * Tn + qt * 64;

    prefetch_kv(sb, SM_B1, tid, b, kt0);
    CP_COMMIT();

#pragma unroll
    for (int it = 0; it < 4; it++) {
        int f = it * 128 + tid;
        int r = f >> 3, cq = f & 7;
        uint32_t off = (uint32_t)(r * PADH + cq * 8) * 2;
        *(uint4*)(smem + SM_QH + off) =
            *(const uint4*)(g_qh + (size_t)(row0 + r) * Hn + cq * 8);
        *(uint4*)(smem + SM_QL + off) =
            *(const uint4*)(g_ql + (size_t)(row0 + r) * Hn + cq * 8);
    }
#pragma unroll
    for (int it = 0; it < 8; it++) {
        int f = it * 128 + tid;
        int r = f >> 4, cq = (f & 15) << 2;
        float4 v = make_float4(0.f, 0.f, 0.f, 0.f);
        if (r < NREL) v = *(const float4*)(rpe + (size_t)r * Hn + cq);
        uint32_t h0, l0, h1, l1;
        split2(v.x, v.y, h0, l0);
        split2(v.z, v.w, h1, l1);
        uint32_t off = (uint32_t)(r * PADH + cq) * 2;
        *(uint2*)(smem + SM_B0 + off) = make_uint2(h0, h1);
        *(uint2*)(smem + SM_B0 + 9216 + off) = make_uint2(l0, l1);
    }
    __syncthreads();

    // ---- bias GEMM: Ds = Q E^T ----
    {
        float dacc[8][4];
#pragma unroll
        for (int nt = 0; nt < 8; nt++)
#pragma unroll
            for (int e = 0; e < 4; e++) dacc[nt][e] = 0.f;
#pragma unroll
        for (int ks = 0; ks < 4; ks++) {
            const int K = ks * 16;
            uint32_t ah[4], al[4];
            uint32_t ao = (uint32_t)((wq + arow_off) * PADH + K + akoff) * 2;
            LDM_X4(ah[0], ah[1], ah[2], ah[3], sb + SM_QH + ao);
            LDM_X4(al[0], al[1], al[2], al[3], sb + SM_QL + ao);
#pragma unroll
            for (int np = 0; np < 4; np++) {
                uint32_t bo = (uint32_t)((np * 16 + bq_row) * PADH + K + bq_col) * 2;
                uint32_t eh[4], el[4];
                LDM_X4(eh[0], eh[1], eh[2], eh[3], sb + SM_B0 + bo);
                LDM_X4(el[0], el[1], el[2], el[3], sb + SM_B0 + 9216 + bo);
                MMA_BF16(dacc[2 * np], ah, eh);
                MMA_BF16(dacc[2 * np], ah, el);
                MMA_BF16(dacc[2 * np], al, eh);
                MMA_BF16(dacc[2 * np + 1], ah, eh + 2);
                MMA_BF16(dacc[2 * np + 1], ah, el + 2);
                MMA_BF16(dacc[2 * np + 1], al, eh + 2);
            }
        }
#pragma unroll
        for (int nt = 0; nt < 8; nt++) {
            int col = nt * 8 + 2 * t;
            *(float2*)&Ds[(wq + g) * 68 + col] =
                make_float2(dacc[nt][0], dacc[nt][1]);
            *(float2*)&Ds[(wq + g + 8) * 68 + col] =
                make_float2(dacc[nt][2], dacc[nt][3]);
        }
    }

    float m0 = -INFINITY, m1 = -INFINITY, l0 = 0.f, l1 = 0.f;
    float oacc[8][4];
#pragma unroll
    for (int nt = 0; nt < 8; nt++)
#pragma unroll
        for (int e = 0; e < 4; e++) oacc[nt][e] = 0.f;

    const int lr0 = wq + g, lr1 = wq + g + 8;
    const int tg0 = qt * 64 + lr0, tg1 = qt * 64 + lr1;

    for (int i = 0; i <= kt1 - kt0; i++) {
        const int kt = kt0 + i;
        const uint32_t cur = (i & 1) ? SM_B0 : SM_B1;

        CP_WAIT0();
        __syncthreads();
        if (kt < kt1) {
            prefetch_kv(sb, (i & 1) ? SM_B1 : SM_B0, tid, b, kt + 1);
            CP_COMMIT();
        }

        float sacc[8][4];
#pragma unroll
        for (int nt = 0; nt < 8; nt++)
#pragma unroll
            for (int e = 0; e < 4; e++) sacc[nt][e] = 0.f;
#pragma unroll
        for (int ks = 0; ks < 4; ks++) {
            const int K = ks * 16;
            uint32_t ah[4], al[4];
            uint32_t ao = (uint32_t)((wq + arow_off) * PADH + K + akoff) * 2;
            LDM_X4(ah[0], ah[1], ah[2], ah[3], sb + SM_QH + ao);
            LDM_X4(al[0], al[1], al[2], al[3], sb + SM_QL + ao);
#pragma unroll
            for (int np = 0; np < 4; np++) {
                uint32_t bo = (uint32_t)((np * 16 + bq_row) * PADH + K + bq_col) * 2;
                uint32_t kh[4], kl[4];
                LDM_X4(kh[0], kh[1], kh[2], kh[3], sb + cur + bo);
                LDM_X4(kl[0], kl[1], kl[2], kl[3], sb + cur + 9216 + bo);
                MMA_BF16(sacc[2 * np], ah, kh);
                MMA_BF16(sacc[2 * np], ah, kl);
                MMA_BF16(sacc[2 * np], al, kh);
                MMA_BF16(sacc[2 * np + 1], ah, kh + 2);
                MMA_BF16(sacc[2 * np + 1], ah, kl + 2);
                MMA_BF16(sacc[2 * np + 1], al, kh + 2);
            }
        }

#pragma unroll
        for (int nt = 0; nt < 8; nt++) {
            const int s0g = kt * 64 + nt * 8 + 2 * t;
#pragma unroll
            for (int e = 0; e < 4; e++) {
                const int sg = s0g + (e & 1);
                const int tg = (e < 2) ? tg0 : tg1;
                const int lr = (e < 2) ? lr0 : lr1;
                int rel = 49 + sg - tg;
                rel = rel < 0 ? 0 : (rel > 49 ? 49 : rel);
                float bias = Ds[lr * 68 + rel];
                sacc[nt][e] = (sg > tg) ? -INFINITY
                                        : fmaf(sacc[nt][e], QK_SCALE, bias);
            }
        }

        float mx0 = -INFINITY, mx1 = -INFINITY;
#pragma unroll
        for (int nt = 0; nt < 8; nt++) {
            mx0 = fmaxf(mx0, fmaxf(sacc[nt][0], sacc[nt][1]));
            mx1 = fmaxf(mx1, fmaxf(sacc[nt][2], sacc[nt][3]));
        }
        mx0 = fmaxf(mx0, __shfl_xor_sync(0xffffffffu, mx0, 1));
        mx0 = fmaxf(mx0, __shfl_xor_sync(0xffffffffu, mx0, 2));
        mx1 = fmaxf(mx1, __shfl_xor_sync(0xffffffffu, mx1, 1));
        mx1 = fmaxf(mx1, __shfl_xor_sync(0xffffffffu, mx1, 2));
        float mn0 = fmaxf(m0, mx0), mn1 = fmaxf(m1, mx1);
        float corr0 = __expf(m0 - mn0), corr1 = __expf(m1 - mn1);
        float s0 = 0.f, s1 = 0.f;
#pragma unroll
        for (int nt = 0; nt < 8; nt++) {
            sacc[nt][0] = __expf(sacc[nt][0] - mn0);
            sacc[nt][1] = __expf(sacc[nt][1] - mn0);
            sacc[nt][2] = __expf(sacc[nt][2] - mn1);
            sacc[nt][3] = __expf(sacc[nt][3] - mn1);
            s0 += sacc[nt][0] + sacc[nt][1];
            s1 += sacc[nt][2] + sacc[nt][3];
        }
        s0 += __shfl_xor_sync(0xffffffffu, s0, 1);
        s0 += __shfl_xor_sync(0xffffffffu, s0, 2);
        s1 += __shfl_xor_sync(0xffffffffu, s1, 1);
        s1 += __shfl_xor_sync(0xffffffffu, s1, 2);
        l0 = l0 * corr0 + s0; m0 = mn0;
        l1 = l1 * corr1 + s1; m1 = mn1;
#pragma unroll
        for (int nt = 0; nt < 8; nt++) {
            oacc[nt][0] *= corr0; oacc[nt][1] *= corr0;
            oacc[nt][2] *= corr1; oacc[nt][3] *= corr1;
        }

#pragma unroll
        for (int ks = 0; ks < 4; ks++) {
            uint32_t ph[4], pl[4];
            split2(sacc[2 * ks][0],     sacc[2 * ks][1],     ph[0], pl[0]);
            split2(sacc[2 * ks][2],     sacc[2 * ks][3],     ph[1], pl[1]);
            split2(sacc[2 * ks + 1][0], sacc[2 * ks + 1][1], ph[2], pl[2]);
            split2(sacc[2 * ks + 1][2], sacc[2 * ks + 1][3], ph[3], pl[3]);
            const int K = ks * 16;
#pragma unroll
            for (int np = 0; np < 4; np++) {
                uint32_t bo = (uint32_t)((np * 16 + bq_row) * PADH + K + bq_col) * 2;
                uint32_t vh[4], vl[4];
                LDM_X4(vh[0], vh[1], vh[2], vh[3], sb + cur + 18432 + bo);
                LDM_X4(vl[0], vl[1], vl[2], vl[3], sb + cur + 27648 + bo);
                MMA_BF16(oacc[2 * np], ph, vh);
                MMA_BF16(oacc[2 * np], ph, vl);
                MMA_BF16(oacc[2 * np], pl, vh);
                MMA_BF16(oacc[2 * np + 1], ph, vh + 2);
                MMA_BF16(oacc[2 * np + 1], ph, vl + 2);
                MMA_BF16(oacc[2 * np + 1], pl, vh + 2);
            }
        }
    }

    if (nch == 1) {
        float i0 = 1.f / l0, i1 = 1.f / l1;
#pragma unroll
        for (int nt = 0; nt < 8; nt++) {
            int col = nt * 8 + 2 * t;
            *(float2*)(out + (size_t)(row0 + lr0) * Hn + col) =
                make_float2(oacc[nt][0] * i0, oacc[nt][1] * i0);
            *(float2*)(out + (size_t)(row0 + lr1) * Hn + col) =
                make_float2(oacc[nt][2] * i1, oacc[nt][3] * i1);
        }
        return;
    }

    const int slot = (b * NQT + qt) * NCH + ch;
    float* pa = g_pacc[slot];
#pragma unroll
    for (int nt = 0; nt < 8; nt++) {
        int col = nt * 8 + 2 * t;
        *(float2*)(pa + lr0 * 64 + col) = make_float2(oacc[nt][0], oacc[nt][1]);
        *(float2*)(pa + lr1 * 64 + col) = make_float2(oacc[nt][2], oacc[nt][3]);
    }
    if (t == 0) {
        g_pm[slot][lr0] = m0; g_pm[slot][lr1] = m1;
        g_pl[slot][lr0] = l0; g_pl[slot][lr1] = l1;
    }
}

// ---------------------------------------------------------------------------
// Combine partials. grid (14, 8) for qt=2..15, 1024 threads.
// Fully unrolled 8-way predicated loads -> one latency round.
// ---------------------------------------------------------------------------
__global__ __launch_bounds__(1024) void combine_kernel(float* __restrict__ out)
{
    const int qt = blockIdx.x + 2, b = blockIdx.y;
    const int nch = (qt >> 1) + 1;
    const int base = (b * NQT + qt) * NCH;
    const int tid = threadIdx.x;
    const int r = tid >> 4;
    const int hc = (tid & 15) << 2;

    float m[NCH], l[NCH];
    float4 v[NCH];
#pragma unroll
    for (int c = 0; c < NCH; c++) {
        bool p = c < nch;
        m[c] = p ? g_pm[base + c][r] : -INFINITY;
        l[c] = p ? g_pl[base + c][r] : 0.f;
        v[c] = p ? *(const float4*)(g_pacc[base + c] + r * 64 + hc)
                 : make_float4(0.f, 0.f, 0.f, 0.f);
    }
    float M = -INFINITY;
#pragma unroll
    for (int c = 0; c < NCH; c++) M = fmaxf(M, m[c]);
    float wgt[NCH], L = 0.f;
#pragma unroll
    for (int c = 0; c < NCH; c++) {
        wgt[c] = __expf(m[c] - M);
        L = fmaf(l[c], wgt[c], L);
    }
    float invL = 1.f / L;
    float4 o = make_float4(0.f, 0.f, 0.f, 0.f);
#pragma unroll
    for (int c = 0; c < NCH; c++) {
        float wc = wgt[c] * invL;
        o.x = fmaf(wc, v[c].x, o.x);
        o.y = fmaf(wc, v[c].y, o.y);
        o.z = fmaf(wc, v[c].z, o.z);
        o.w = fmaf(wc, v[c].w, o.w);
    }
    *(float4*)(out + (size_t)(b * Tn + qt * 64 + r) * Hn + hc) = o;
}

extern "C" void kernel_launch(void* const* d_in, const int* in_sizes, int n_in,
                              void* d_out, int out_size)
{
    const float* x   = (const float*)d_in[0];
    const float* Wq  = (const float*)d_in[1];
    const float* Wk  = (const float*)d_in[2];
    const float* Wv  = (const float*)d_in[3];
    const float* rpe = (const float*)d_in[4];
    float* out = (float*)d_out;

    cudaFuncSetAttribute(qkv_mma_kernel,
                         cudaFuncAttributeMaxDynamicSharedMemorySize, QKV_SMEM);
    cudaFuncSetAttribute(attn_part_kernel,
                         cudaFuncAttributeMaxDynamicSharedMemorySize, ATTN_SMEM);

    cvt_w_kernel<<<24, 1024>>>(Wq, Wk, Wv);
    qkv_mma_kernel<<<128, 256, QKV_SMEM>>>(x);
    attn_part_kernel<<<dim3(NWORK, 8), 128, ATTN_SMEM>>>(rpe, out);
    combine_kernel<<<dim3(14, 8), 1024>>>(out);
}

// round 14
// speedup vs baseline: 1.0782x; 1.0196x over previous
#include <cuda_runtime.h>
#include <cuda_bf16.h>
#include <math.h>
#include <stdint.h>

#define Bn 8
#define Tn 1024
#define Cn 512
#define Hn 64
#define NREL 50
#define QK_SCALE 0.125f   // 64^-0.5
#define NQT 16
#define NCH 8             // max kv-chunks per q-tile (128 keys per chunk)
#define NWORK 72          // sum over qt of ceil((qt+1)/2)

// split-bf16 q,k (row-major [B*T][64]) and v transposed ([B][64][T])
__device__ __nv_bfloat16 g_qh[Bn * Tn * Hn];
__device__ __nv_bfloat16 g_ql[Bn * Tn * Hn];
__device__ __nv_bfloat16 g_kh[Bn * Tn * Hn];
__device__ __nv_bfloat16 g_kl[Bn * Tn * Hn];
__device__ __nv_bfloat16 g_vth[Bn * Hn * Tn];
__device__ __nv_bfloat16 g_vtl[Bn * Hn * Tn];

// split-bf16 W^T
__device__ __nv_bfloat16 g_wth[192 * Cn];
__device__ __nv_bfloat16 g_wtl[192 * Cn];

// split-KV partials
__device__ float g_pacc[Bn * NQT * NCH][64 * 64];
__device__ float g_pm[Bn * NQT * NCH][64];
__device__ float g_pl[Bn * NQT * NCH][64];

__constant__ unsigned char c_qt[NWORK] = {
    0, 1, 2,2, 3,3, 4,4,4, 5,5,5,
    6,6,6,6, 7,7,7,7, 8,8,8,8,8, 9,9,9,9,9,
    10,10,10,10,10,10, 11,11,11,11,11,11,
    12,12,12,12,12,12,12, 13,13,13,13,13,13,13,
    14,14,14,14,14,14,14,14, 15,15,15,15,15,15,15,15};
__constant__ unsigned char c_ch[NWORK] = {
    0, 0, 0,1, 0,1, 0,1,2, 0,1,2,
    0,1,2,3, 0,1,2,3, 0,1,2,3,4, 0,1,2,3,4,
    0,1,2,3,4,5, 0,1,2,3,4,5,
    0,1,2,3,4,5,6, 0,1,2,3,4,5,6,
    0,1,2,3,4,5,6,7, 0,1,2,3,4,5,6,7};

// ---------------------------------------------------------------------------
// helpers
// ---------------------------------------------------------------------------
__device__ __forceinline__ uint32_t smem_u32(const void* p) {
    uint32_t a;
    asm("{ .reg .u64 t; cvta.to.shared.u64 t, %1; cvt.u32.u64 %0, t; }"
        : "=r"(a) : "l"(p));
    return a;
}
#define LDM_X4(r0, r1, r2, r3, a) \
    asm volatile("ldmatrix.sync.aligned.m8n8.x4.shared.b16 {%0,%1,%2,%3}, [%4];" \
                 : "=r"(r0), "=r"(r1), "=r"(r2), "=r"(r3) : "r"(a))
#define LDM_X2(r0, r1, a) \
    asm volatile("ldmatrix.sync.aligned.m8n8.x2.shared.b16 {%0,%1}, [%2];" \
                 : "=r"(r0), "=r"(r1) : "r"(a))
#define MMA_BF16(d, a, b) \
    asm volatile("mma.sync.aligned.m16n8k16.row.col.f32.bf16.bf16.f32 " \
                 "{%0,%1,%2,%3}, {%4,%5,%6,%7}, {%8,%9}, {%0,%1,%2,%3};" \
                 : "+f"((d)[0]), "+f"((d)[1]), "+f"((d)[2]), "+f"((d)[3]) \
                 : "r"((a)[0]), "r"((a)[1]), "r"((a)[2]), "r"((a)[3]), \
                   "r"((b)[0]), "r"((b)[1]))

__device__ __forceinline__ void cp16(uint32_t s, const void* g) {
    asm volatile("cp.async.cg.shared.global [%0], [%1], 16;" :: "r"(s), "l"(g));
}
#define CP_COMMIT() asm volatile("cp.async.commit_group;" ::: "memory")
#define CP_WAIT0()  asm volatile("cp.async.wait_group 0;" ::: "memory")

__device__ __forceinline__ void split2(float f0, float f1,
                                       uint32_t& h, uint32_t& l) {
    __nv_bfloat16 h0 = __float2bfloat16(f0), h1 = __float2bfloat16(f1);
    __nv_bfloat16 l0 = __float2bfloat16(f0 - __bfloat162float(h0));
    __nv_bfloat16 l1 = __float2bfloat16(f1 - __bfloat162float(h1));
    __nv_bfloat162 hh(h0, h1), ll(l0, l1);
    h = *(uint32_t*)&hh; l = *(uint32_t*)&ll;
}

// ---------------------------------------------------------------------------
// Weight convert + transpose. grid 24, 1024 threads.
// ---------------------------------------------------------------------------
__global__ __launch_bounds__(1024) void cvt_w_kernel(
    const float* __restrict__ Wq, const float* __restrict__ Wk,
    const float* __restrict__ Wv)
{
    __shared__ __nv_bfloat16 th[64][72];   // [n][k]
    __shared__ __nv_bfloat16 tl[64][72];
    const int mat = blockIdx.x >> 3, kt = blockIdx.x & 7;
    const float* W = (mat == 0) ? Wq : (mat == 1 ? Wk : Wv);
    const int tid = threadIdx.x;

    {
        int k = tid >> 4, nn = (tid & 15) << 2;
        float4 v = *(const float4*)(W + (size_t)(kt * 64 + k) * Hn + nn);
        float vv[4] = {v.x, v.y, v.z, v.w};
#pragma unroll
        for (int j = 0; j < 4; j++) {
            __nv_bfloat16 h = __float2bfloat16(vv[j]);
            th[nn + j][k] = h;
            tl[nn + j][k] = __float2bfloat16(vv[j] - __bfloat162float(h));
        }
    }
    __syncthreads();
    {
        int n = (tid & 511) >> 3, kk = (tid & 7) << 3;
        size_t dst = (size_t)(mat * 64 + n) * Cn + kt * 64 + kk;
        if (tid < 512) *(uint4*)(g_wth + dst) = *(uint4*)&th[n][kk];
        else           *(uint4*)(g_wtl + dst) = *(uint4*)&tl[n][kk];
    }
}

// ---------------------------------------------------------------------------
// QKV projection on mma.sync bf16 (split hi/lo). grid 128, 512 threads.
// 16 warps (4 wm x 4 wn); warp tile 16 rows x 48 cols.
// ---------------------------------------------------------------------------
#define PAD 72
#define SM_AH 0
#define SM_AL 9216
#define SM_BH 18432
#define SM_BL 46080
#define QKV_SMEM 73728

__global__ __launch_bounds__(512, 1) void qkv_mma_kernel(const float* __restrict__ x)
{
    extern __shared__ char smem[];
    const uint32_t sb = smem_u32(smem);
    const int tid = threadIdx.x;
    const int wid = tid >> 5, lane = tid & 31;
    const int wm = wid >> 2, wn = wid & 3;
    const int m0 = blockIdx.x * 64;

    float acc[6][4];
#pragma unroll
    for (int nt = 0; nt < 6; nt++)
#pragma unroll
        for (int e = 0; e < 4; e++) acc[nt][e] = 0.f;

    const int aq = lane >> 3, ai = lane & 7;
    const int arow_off = (aq & 1) * 8 + ai;
    const int akoff = (aq >> 1) * 8;
    const int bi = lane & 7, bh8 = ((lane >> 3) & 1) * 8;

    for (int c = 0; c < 8; c++) {
        if (c) __syncthreads();
        const int kc = c * 64;
        // A: 64 rows x 64 k fp32 -> hi/lo bf16 smem (1024 float4 / 512 thr)
#pragma unroll
        for (int it = 0; it < 2; it++) {
            int f = it * 512 + tid;
            int r = f >> 4, kq = (f & 15) << 2;
            float4 v = *(const float4*)(x + (size_t)(m0 + r) * Cn + kc + kq);
            uint32_t h0, l0, h1, l1;
            split2(v.x, v.y, h0, l0);
            split2(v.z, v.w, h1, l1);
            uint32_t off = (uint32_t)(r * PAD + kq) * 2;
            *(uint2*)(smem + SM_AH + off) = make_uint2(h0, h1);
            *(uint2*)(smem + SM_AL + off) = make_uint2(l0, l1);
        }
        // B: 192 rows x 64 k bf16 copy (1536 uint4 / 512 thr)
#pragma unroll
        for (int it = 0; it < 3; it++) {
            int f = it * 512 + tid;
            int n = f >> 3, kq = (f & 7) << 3;
            uint32_t off = (uint32_t)(n * PAD + kq) * 2;
            *(uint4*)(smem + SM_BH + off) =
                *(const uint4*)(g_wth + (size_t)n * Cn + kc + kq);
            *(uint4*)(smem + SM_BL + off) =
                *(const uint4*)(g_wtl + (size_t)n * Cn + kc + kq);
        }
        __syncthreads();

#pragma unroll
        for (int ks = 0; ks < 4; ks++) {
            const int K = ks * 16;
            uint32_t ah[4], al[4];
            uint32_t ao = (uint32_t)((wm * 16 + arow_off) * PAD + K + akoff) * 2;
            LDM_X4(ah[0], ah[1], ah[2], ah[3], sb + SM_AH + ao);
            LDM_X4(al[0], al[1], al[2], al[3], sb + SM_AL + ao);
#pragma unroll
            for (int nt = 0; nt < 6; nt++) {
                uint32_t bo = (uint32_t)((wn * 48 + nt * 8 + bi) * PAD
                                         + K + bh8) * 2;
                uint32_t bh[2], bl[2];
                LDM_X2(bh[0], bh[1], sb + SM_BH + bo);
                LDM_X2(bl[0], bl[1], sb + SM_BL + bo);
                MMA_BF16(acc[nt], ah, bh);
                MMA_BF16(acc[nt], ah, bl);
                MMA_BF16(acc[nt], al, bh);
            }
        }
    }

    const int g = lane >> 2, t = lane & 3;
#pragma unroll
    for (int nt = 0; nt < 6; nt++) {
        const int c0 = wn * 48 + nt * 8 + 2 * t;
        const size_t row = (size_t)m0 + wm * 16 + g;
        if (c0 < 128) {
            __nv_bfloat16* dh = (c0 < 64) ? g_qh : g_kh;
            __nv_bfloat16* dl = (c0 < 64) ? g_ql : g_kl;
            const int cc = c0 & 63;
            uint32_t h, l;
            split2(acc[nt][0], acc[nt][1], h, l);
            *(uint32_t*)(dh + row * Hn + cc) = h;
            *(uint32_t*)(dl + row * Hn + cc) = l;
            split2(acc[nt][2], acc[nt][3], h, l);
            *(uint32_t*)(dh + (row + 8) * Hn + cc) = h;
            *(uint32_t*)(dl + (row + 8) * Hn + cc) = l;
        } else {
            const int cc = c0 - 128;
            const size_t bb = row >> 10;
#pragma unroll
            for (int rr = 0; rr < 2; rr++) {
                const size_t s = (row + rr * 8) & 1023;
                float f0 = acc[nt][rr * 2], f1 = acc[nt][rr * 2 + 1];
                __nv_bfloat16 h0 = __float2bfloat16(f0);
                __nv_bfloat16 h1 = __float2bfloat16(f1);
                g_vth[bb * 65536 + (size_t)cc * 1024 + s] = h0;
                g_vtl[bb * 65536 + (size_t)cc * 1024 + s] =
                    __float2bfloat16(f0 - __bfloat162float(h0));
                g_vth[bb * 65536 + (size_t)(cc + 1) * 1024 + s] = h1;
                g_vtl[bb * 65536 + (size_t)(cc + 1) * 1024 + s] =
                    __float2bfloat16(f1 - __bfloat162float(h1));
            }
        }
    }
}

// ---------------------------------------------------------------------------
// Fragment-resident flash attention, cp.async double-buffered K/V.
// grid (72, 8), 128 threads. Chunk = up to 2 key-tiles. (R13 unchanged)
// ---------------------------------------------------------------------------
#define PADH 72
#define SM_QH  0
#define SM_QL  9216
#define SM_B0  18432
#define SM_B1  55296
#define SM_DS  92160
#define ATTN_SMEM 109568

__device__ __forceinline__ void prefetch_kv(uint32_t sb, uint32_t buf,
                                            int tid, int b, int kt)
{
    const int krow0 = b * Tn + kt * 64;
#pragma unroll
    for (int it = 0; it < 4; it++) {
        int f = it * 128 + tid;
        int r = f >> 3, cq = f & 7;
        uint32_t off = (uint32_t)(r * PADH + cq * 8) * 2;
        cp16(sb + buf + off,
             g_kh + (size_t)(krow0 + r) * Hn + cq * 8);
        cp16(sb + buf + 9216 + off,
             g_kl + (size_t)(krow0 + r) * Hn + cq * 8);
        cp16(sb + buf + 18432 + off,
             g_vth + (size_t)b * 65536 + (size_t)r * 1024 + kt * 64 + cq * 8);
        cp16(sb + buf + 27648 + off,
             g_vtl + (size_t)b * 65536 + (size_t)r * 1024 + kt * 64 + cq * 8);
    }
}

__global__ __launch_bounds__(128) void attn_part_kernel(
    const float* __restrict__ rpe, float* __restrict__ out)
{
    extern __shared__ char smem[];
    const uint32_t sb = smem_u32(smem);
    float* Ds = (float*)(smem + SM_DS);

    const int w = blockIdx.x, b = blockIdx.y;
    const int qt = c_qt[w], ch = c_ch[w];
    const int kt0 = ch * 2;
    const int kt1 = min(qt, kt0 + 1);
    const int nch = (qt >> 1) + 1;

    const int tid = threadIdx.x;
    const int wid = tid >> 5, lane = tid & 31;
    const int g = lane >> 2, t = lane & 3;
    const int aq = lane >> 3, ai = lane & 7;
    const int arow_off = (aq & 1) * 8 + ai;
    const int akoff = (aq >> 1) * 8;
    const int bq_row = ((lane >> 4) & 1) * 8 + (lane & 7);
    const int bq_col = ((lane >> 3) & 1) * 8;
    const int wq = wid * 16;
    const int row0 = b * Tn + qt * 64;

    prefetch_kv(sb, SM_B1, tid, b, kt0);
    CP_COMMIT();

#pragma unroll
    for (int it = 0; it < 4; it++) {
        int f = it * 128 + tid;
        int r = f >> 3, cq = f & 7;
        uint32_t off = (uint32_t)(r * PADH + cq * 8) * 2;
        *(uint4*)(smem + SM_QH + off) =
            *(const uint4*)(g_qh + (size_t)(row0 + r) * Hn + cq * 8);
        *(uint4*)(smem + SM_QL + off) =
            *(const uint4*)(g_ql + (size_t)(row0 + r) * Hn + cq * 8);
    }
#pragma unroll
    for (int it = 0; it < 8; it++) {
        int f = it * 128 + tid;
        int r = f >> 4, cq = (f & 15) << 2;
        float4 v = make_float4(0.f, 0.f, 0.f, 0.f);
        if (r < NREL) v = *(const float4*)(rpe + (size_t)r * Hn + cq);
        uint32_t h0, l0, h1, l1;
        split2(v.x, v.y, h0, l0);
        split2(v.z, v.w, h1, l1);
        uint32_t off = (uint32_t)(r * PADH + cq) * 2;
        *(uint2*)(smem + SM_B0 + off) = make_uint2(h0, h1);
        *(uint2*)(smem + SM_B0 + 9216 + off) = make_uint2(l0, l1);
    }
    __syncthreads();

    // ---- bias GEMM: Ds = Q E^T ----
    {
        float dacc[8][4];
#pragma unroll
        for (int nt = 0; nt < 8; nt++)
#pragma unroll
            for (int e = 0; e < 4; e++) dacc[nt][e] = 0.f;
#pragma unroll
        for (int ks = 0; ks < 4; ks++) {
            const int K = ks * 16;
            uint32_t ah[4], al[4];
            uint32_t ao = (uint32_t)((wq + arow_off) * PADH + K + akoff) * 2;
            LDM_X4(ah[0], ah[1], ah[2], ah[3], sb + SM_QH + ao);
            LDM_X4(al[0], al[1], al[2], al[3], sb + SM_QL + ao);
#pragma unroll
            for (int np = 0; np < 4; np++) {
                uint32_t bo = (uint32_t)((np * 16 + bq_row) * PADH + K + bq_col) * 2;
                uint32_t eh[4], el[4];
                LDM_X4(eh[0], eh[1], eh[2], eh[3], sb + SM_B0 + bo);
                LDM_X4(el[0], el[1], el[2], el[3], sb + SM_B0 + 9216 + bo);
                MMA_BF16(dacc[2 * np], ah, eh);
                MMA_BF16(dacc[2 * np], ah, el);
                MMA_BF16(dacc[2 * np], al, eh);
                MMA_BF16(dacc[2 * np + 1], ah, eh + 2);
                MMA_BF16(dacc[2 * np + 1], ah, el + 2);
                MMA_BF16(dacc[2 * np + 1], al, eh + 2);
            }
        }
#pragma unroll
        for (int nt = 0; nt < 8; nt++) {
            int col = nt * 8 + 2 * t;
            *(float2*)&Ds[(wq + g) * 68 + col] =
                make_float2(dacc[nt][0], dacc[nt][1]);
            *(float2*)&Ds[(wq + g + 8) * 68 + col] =
                make_float2(dacc[nt][2], dacc[nt][3]);
        }
    }

    float m0 = -INFINITY, m1 = -INFINITY, l0 = 0.f, l1 = 0.f;
    float oacc[8][4];
#pragma unroll
    for (int nt = 0; nt < 8; nt++)
#pragma unroll
        for (int e = 0; e < 4; e++) oacc[nt][e] = 0.f;

    const int lr0 = wq + g, lr1 = wq + g + 8;
    const int tg0 = qt * 64 + lr0, tg1 = qt * 64 + lr1;

    for (int i = 0; i <= kt1 - kt0; i++) {
        const int kt = kt0 + i;
        const uint32_t cur = (i & 1) ? SM_B0 : SM_B1;

        CP_WAIT0();
        __syncthreads();
        if (kt < kt1) {
            prefetch_kv(sb, (i & 1) ? SM_B1 : SM_B0, tid, b, kt + 1);
            CP_COMMIT();
        }

        float sacc[8][4];
#pragma unroll
        for (int nt = 0; nt < 8; nt++)
#pragma unroll
            for (int e = 0; e < 4; e++) sacc[nt][e] = 0.f;
#pragma unroll
        for (int ks = 0; ks < 4; ks++) {
            const int K = ks * 16;
            uint32_t ah[4], al[4];
            uint32_t ao = (uint32_t)((wq + arow_off) * PADH + K + akoff) * 2;
            LDM_X4(ah[0], ah[1], ah[2], ah[3], sb + SM_QH + ao);
            LDM_X4(al[0], al[1], al[2], al[3], sb + SM_QL + ao);
#pragma unroll
            for (int np = 0; np < 4; np++) {
                uint32_t bo = (uint32_t)((np * 16 + bq_row) * PADH + K + bq_col) * 2;
                uint32_t kh[4], kl[4];
                LDM_X4(kh[0], kh[1], kh[2], kh[3], sb + cur + bo);
                LDM_X4(kl[0], kl[1], kl[2], kl[3], sb + cur + 9216 + bo);
                MMA_BF16(sacc[2 * np], ah, kh);
                MMA_BF16(sacc[2 * np], ah, kl);
                MMA_BF16(sacc[2 * np], al, kh);
                MMA_BF16(sacc[2 * np + 1], ah, kh + 2);
                MMA_BF16(sacc[2 * np + 1], ah, kl + 2);
                MMA_BF16(sacc[2 * np + 1], al, kh + 2);
            }
        }

#pragma unroll
        for (int nt = 0; nt < 8; nt++) {
            const int s0g = kt * 64 + nt * 8 + 2 * t;
#pragma unroll
            for (int e = 0; e < 4; e++) {
                const int sg = s0g + (e & 1);
                const int tg = (e < 2) ? tg0 : tg1;
                const int lr = (e < 2) ? lr0 : lr1;
                int rel = 49 + sg - tg;
                rel = rel < 0 ? 0 : (rel > 49 ? 49 : rel);
                float bias = Ds[lr * 68 + rel];
                sacc[nt][e] = (sg > tg) ? -INFINITY
                                        : fmaf(sacc[nt][e], QK_SCALE, bias);
            }
        }

        float mx0 = -INFINITY, mx1 = -INFINITY;
#pragma unroll
        for (int nt = 0; nt < 8; nt++) {
            mx0 = fmaxf(mx0, fmaxf(sacc[nt][0], sacc[nt][1]));
            mx1 = fmaxf(mx1, fmaxf(sacc[nt][2], sacc[nt][3]));
        }
        mx0 = fmaxf(mx0, __shfl_xor_sync(0xffffffffu, mx0, 1));
        mx0 = fmaxf(mx0, __shfl_xor_sync(0xffffffffu, mx0, 2));
        mx1 = fmaxf(mx1, __shfl_xor_sync(0xffffffffu, mx1, 1));
        mx1 = fmaxf(mx1, __shfl_xor_sync(0xffffffffu, mx1, 2));
        float mn0 = fmaxf(m0, mx0), mn1 = fmaxf(m1, mx1);
        float corr0 = __expf(m0 - mn0), corr1 = __expf(m1 - mn1);
        float s0 = 0.f, s1 = 0.f;
#pragma unroll
        for (int nt = 0; nt < 8; nt++) {
            sacc[nt][0] = __expf(sacc[nt][0] - mn0);
            sacc[nt][1] = __expf(sacc[nt][1] - mn0);
            sacc[nt][2] = __expf(sacc[nt][2] - mn1);
            sacc[nt][3] = __expf(sacc[nt][3] - mn1);
            s0 += sacc[nt][0] + sacc[nt][1];
            s1 += sacc[nt][2] + sacc[nt][3];
        }
        s0 += __shfl_xor_sync(0xffffffffu, s0, 1);
        s0 += __shfl_xor_sync(0xffffffffu, s0, 2);
        s1 += __shfl_xor_sync(0xffffffffu, s1, 1);
        s1 += __shfl_xor_sync(0xffffffffu, s1, 2);
        l0 = l0 * corr0 + s0; m0 = mn0;
        l1 = l1 * corr1 + s1; m1 = mn1;
#pragma unroll
        for (int nt = 0; nt < 8; nt++) {
            oacc[nt][0] *= corr0; oacc[nt][1] *= corr0;
            oacc[nt][2] *= corr1; oacc[nt][3] *= corr1;
        }

#pragma unroll
        for (int ks = 0; ks < 4; ks++) {
            uint32_t ph[4], pl[4];
            split2(sacc[2 * ks][0],     sacc[2 * ks][1],     ph[0], pl[0]);
            split2(sacc[2 * ks][2],     sacc[2 * ks][3],     ph[1], pl[1]);
            split2(sacc[2 * ks + 1][0], sacc[2 * ks + 1][1], ph[2], pl[2]);
            split2(sacc[2 * ks + 1][2], sacc[2 * ks + 1][3], ph[3], pl[3]);
            const int K = ks * 16;
#pragma unroll
            for (int np = 0; np < 4; np++) {
                uint32_t bo = (uint32_t)((np * 16 + bq_row) * PADH + K + bq_col) * 2;
                uint32_t vh[4], vl[4];
                LDM_X4(vh[0], vh[1], vh[2], vh[3], sb + cur + 18432 + bo);
                LDM_X4(vl[0], vl[1], vl[2], vl[3], sb + cur + 27648 + bo);
                MMA_BF16(oacc[2 * np], ph, vh);
                MMA_BF16(oacc[2 * np], ph, vl);
                MMA_BF16(oacc[2 * np], pl, vh);
                MMA_BF16(oacc[2 * np + 1], ph, vh + 2);
                MMA_BF16(oacc[2 * np + 1], ph, vl + 2);
                MMA_BF16(oacc[2 * np + 1], pl, vh + 2);
            }
        }
    }

    if (nch == 1) {
        float i0 = 1.f / l0, i1 = 1.f / l1;
#pragma unroll
        for (int nt = 0; nt < 8; nt++) {
            int col = nt * 8 + 2 * t;
            *(float2*)(out + (size_t)(row0 + lr0) * Hn + col) =
                make_float2(oacc[nt][0] * i0, oacc[nt][1] * i0);
            *(float2*)(out + (size_t)(row0 + lr1) * Hn + col) =
                make_float2(oacc[nt][2] * i1, oacc[nt][3] * i1);
        }
        return;
    }

    const int slot = (b * NQT + qt) * NCH + ch;
    float* pa = g_pacc[slot];
#pragma unroll
    for (int nt = 0; nt < 8; nt++) {
        int col = nt * 8 + 2 * t;
        *(float2*)(pa + lr0 * 64 + col) = make_float2(oacc[nt][0], oacc[nt][1]);
        *(float2*)(pa + lr1 * 64 + col) = make_float2(oacc[nt][2], oacc[nt][3]);
    }
    if (t == 0) {
        g_pm[slot][lr0] = m0; g_pm[slot][lr1] = m1;
        g_pl[slot][lr0] = l0; g_pl[slot][lr1] = l1;
    }
}

// ---------------------------------------------------------------------------
// Combine partials. grid (14, 8) for qt=2..15, 1024 threads.
// ---------------------------------------------------------------------------
__global__ __launch_bounds__(1024) void combine_kernel(float* __restrict__ out)
{
    const int qt = blockIdx.x + 2, b = blockIdx.y;
    const int nch = (qt >> 1) + 1;
    const int base = (b * NQT + qt) * NCH;
    const int tid = threadIdx.x;
    const int r = tid >> 4;
    const int hc = (tid & 15) << 2;

    float m[NCH], l[NCH];
    float4 v[NCH];
#pragma unroll
    for (int c = 0; c < NCH; c++) {
        bool p = c < nch;
        m[c] = p ? g_pm[base + c][r] : -INFINITY;
        l[c] = p ? g_pl[base + c][r] : 0.f;
        v[c] = p ? *(const float4*)(g_pacc[base + c] + r * 64 + hc)
                 : make_float4(0.f, 0.f, 0.f, 0.f);
    }
    float M = -INFINITY;
#pragma unroll
    for (int c = 0; c < NCH; c++) M = fmaxf(M, m[c]);
    float wgt[NCH], L = 0.f;
#pragma unroll
    for (int c = 0; c < NCH; c++) {
        wgt[c] = __expf(m[c] - M);
        L = fmaf(l[c], wgt[c], L);
    }
    float invL = 1.f / L;
    float4 o = make_float4(0.f, 0.f, 0.f, 0.f);
#pragma unroll
    for (int c = 0; c < NCH; c++) {
        float wc = wgt[c] * invL;
        o.x = fmaf(wc, v[c].x, o.x);
        o.y = fmaf(wc, v[c].y, o.y);
        o.z = fmaf(wc, v[c].z, o.z);
        o.w = fmaf(wc, v[c].w, o.w);
    }
    *(float4*)(out + (size_t)(b * Tn + qt * 64 + r) * Hn + hc) = o;
}

extern "C" void kernel_launch(void* const* d_in, const int* in_sizes, int n_in,
                              void* d_out, int out_size)
{
    const float* x   = (const float*)d_in[0];
    const float* Wq  = (const float*)d_in[1];
    const float* Wk  = (const float*)d_in[2];
    const float* Wv  = (const float*)d_in[3];
    const float* rpe = (const float*)d_in[4];
    float* out = (float*)d_out;

    cudaFuncSetAttribute(qkv_mma_kernel,
                         cudaFuncAttributeMaxDynamicSharedMemorySize, QKV_SMEM);
    cudaFuncSetAttribute(attn_part_kernel,
                         cudaFuncAttributeMaxDynamicSharedMemorySize, ATTN_SMEM);

    cvt_w_kernel<<<24, 1024>>>(Wq, Wk, Wv);
    qkv_mma_kernel<<<128, 512, QKV_SMEM>>>(x);
    attn_part_kernel<<<dim3(NWORK, 8), 128, ATTN_SMEM>>>(rpe, out);
    combine_kernel<<<dim3(14, 8), 1024>>>(out);
}